// round 2
// baseline (speedup 1.0000x reference)
#include <cuda_runtime.h>

#define NN      131072
#define NG      256
#define INDIM   256
#define HID     512
#define HID2    1024
#define NE      2097152
#define OFF_L   ((size_t)NN * INDIM)      /* 33554432 : logits section   */
#define OFF_E   (OFF_L + NN)              /* 33685504 : edge-mask section */

// -------- scratch (device globals: allocation-free per harness rules) ------
__device__ float         g_z[(size_t)NN * HID2];   // 512 MB GEMM output
__device__ float         g_logits[NN];
__device__ unsigned char g_keep[NN];
__device__ int           g_start[NG + 1];

// -------- packed fp32x2 helpers (Blackwell sm_103a) -------------------------
__device__ __forceinline__ unsigned long long pack2(float a, float b) {
    unsigned long long r;
    asm("mov.b64 %0, {%1,%2};" : "=l"(r) : "f"(a), "f"(b));
    return r;
}
__device__ __forceinline__ void fma2(unsigned long long& d,
                                     unsigned long long a, unsigned long long b) {
    asm("fma.rn.f32x2 %0, %1, %2, %0;" : "+l"(d) : "l"(a), "l"(b));
}
__device__ __forceinline__ float2 unpack2(unsigned long long v) {
    float2 r;
    asm("mov.b64 {%0,%1}, %2;" : "=f"(r.x), "=f"(r.y) : "l"(v));
    return r;
}

// ============================================================================
// Kernel 1: z = h @ W1 + b1   (131072x512 @ 512x1024, fp32, f32x2 pipe)
// Tile 128x128x16, 256 threads, 8x8 per-thread microtile as 8x4 f32x2 accums.
// A staged into smem transposed AND duplicated: As[k][2m]=As[k][2m+1]=A[m][k],
// so the broadcast operand for fma.rn.f32x2 is a plain LDS.128.
// ============================================================================
__device__ __forceinline__ void storeA_dup(float (*Asb)[256], int kk, int row, float4 v) {
    *(unsigned long long*)&Asb[kk + 0][2 * row] = pack2(v.x, v.x);
    *(unsigned long long*)&Asb[kk + 1][2 * row] = pack2(v.y, v.y);
    *(unsigned long long*)&Asb[kk + 2][2 * row] = pack2(v.z, v.z);
    *(unsigned long long*)&Asb[kk + 3][2 * row] = pack2(v.w, v.w);
}

__global__ __launch_bounds__(256, 2) void gemm1_kernel(
    const float* __restrict__ A,      // h  [NN, 512]
    const float* __restrict__ B,      // W1 [512, 1024]
    const float* __restrict__ bias)   // b1 [1024]
{
    __shared__ __align__(16) float As[2][16][256];
    __shared__ __align__(16) float Bs[2][16][132];

    const int tid = threadIdx.x;
    const int bn = blockIdx.x;        // 8 tiles of N=1024
    const int bm = blockIdx.y;        // 1024 tiles of M=131072
    const int tx = tid & 15, ty = tid >> 4;

    // global-load assignments (2x float4 each for A and B per K-iter)
    const int f0 = tid * 2, f1 = f0 + 1;
    const int ar0 = f0 >> 2, ak0 = (f0 & 3) << 2;
    const int ar1 = f1 >> 2, ak1 = (f1 & 3) << 2;
    const int bk0 = f0 >> 5, bn0 = (f0 & 31) << 2;
    const int bk1 = f1 >> 5, bn1 = (f1 & 31) << 2;

    const float* Ag0 = A + ((size_t)(bm * 128 + ar0)) * HID + ak0;
    const float* Ag1 = A + ((size_t)(bm * 128 + ar1)) * HID + ak1;
    const float* Bg0 = B + (size_t)bk0 * HID2 + bn * 128 + bn0;
    const float* Bg1 = B + (size_t)bk1 * HID2 + bn * 128 + bn1;

    unsigned long long acc[8][4] = {};   // (c[i][2j], c[i][2j+1]) pairs, = 0.0f bits

    float4 va0 = *(const float4*)Ag0;
    float4 va1 = *(const float4*)Ag1;
    float4 vb0 = *(const float4*)Bg0;
    float4 vb1 = *(const float4*)Bg1;

    for (int kt = 0; kt < 32; kt++) {
        const int buf = kt & 1;
        storeA_dup(As[buf], ak0, ar0, va0);
        storeA_dup(As[buf], ak1, ar1, va1);
        *(float4*)&Bs[buf][bk0][bn0] = vb0;
        *(float4*)&Bs[buf][bk1][bn1] = vb1;
        __syncthreads();   // single barrier/iter: store(kt+2,buf) is ordered after
                           // every thread's compute(kt,buf) via sync(kt+1).
        if (kt < 31) {     // register prefetch of next K-tile (hides DRAM latency)
            va0 = *(const float4*)(Ag0 + (kt + 1) * 16);
            va1 = *(const float4*)(Ag1 + (kt + 1) * 16);
            vb0 = *(const float4*)(Bg0 + (size_t)(kt + 1) * 16 * HID2);
            vb1 = *(const float4*)(Bg1 + (size_t)(kt + 1) * 16 * HID2);
        }
        #pragma unroll
        for (int k = 0; k < 16; k++) {
            const ulonglong2* ap = (const ulonglong2*)&As[buf][k][ty * 16];
            const ulonglong2* bp = (const ulonglong2*)&Bs[buf][k][tx * 8];
            ulonglong2 A0 = ap[0], A1 = ap[1], A2 = ap[2], A3 = ap[3];
            ulonglong2 B0 = bp[0], B1 = bp[1];
            unsigned long long av[8] = {A0.x, A0.y, A1.x, A1.y, A2.x, A2.y, A3.x, A3.y};
            unsigned long long bv[4] = {B0.x, B0.y, B1.x, B1.y};
            #pragma unroll
            for (int i = 0; i < 8; i++)
                #pragma unroll
                for (int j = 0; j < 4; j++)
                    fma2(acc[i][j], av[i], bv[j]);
        }
    }

    // epilogue: + bias, store z
    const float* bp = bias + bn * 128 + tx * 8;
    const float4 blo = *(const float4*)bp;
    const float4 bhi = *(const float4*)(bp + 4);
    #pragma unroll
    for (int i = 0; i < 8; i++) {
        float2 c0 = unpack2(acc[i][0]);
        float2 c1 = unpack2(acc[i][1]);
        float2 c2 = unpack2(acc[i][2]);
        float2 c3 = unpack2(acc[i][3]);
        float4 lo = make_float4(c0.x + blo.x, c0.y + blo.y, c1.x + blo.z, c1.y + blo.w);
        float4 hi = make_float4(c2.x + bhi.x, c2.y + bhi.y, c3.x + bhi.z, c3.y + bhi.w);
        const size_t m = (size_t)bm * 128 + ty * 8 + i;
        float* cp = g_z + m * HID2 + bn * 128 + tx * 8;
        *(float4*)cp       = lo;
        *(float4*)(cp + 4) = hi;
    }
}

// ============================================================================
// Kernel 2: per-row LayerNorm -> ReLU -> dot(W2) -> sigmoid.  1 block / row.
// ============================================================================
__device__ __forceinline__ float block_reduce_256(float v, float* sh) {
    #pragma unroll
    for (int o = 16; o > 0; o >>= 1) v += __shfl_down_sync(0xffffffffu, v, o);
    const int lane = threadIdx.x & 31, w = threadIdx.x >> 5;
    if (lane == 0) sh[w] = v;
    __syncthreads();
    if (threadIdx.x < 32) {
        float t = (threadIdx.x < 8) ? sh[threadIdx.x] : 0.0f;
        #pragma unroll
        for (int o = 4; o > 0; o >>= 1) t += __shfl_down_sync(0xffffffffu, t, o);
        if (threadIdx.x == 0) sh[8] = t;
    }
    __syncthreads();
    float r = sh[8];
    __syncthreads();
    return r;
}

__global__ __launch_bounds__(256) void ln_head_kernel(
    const float* __restrict__ gamma, const float* __restrict__ beta,
    const float* __restrict__ W2, const float* __restrict__ b2)
{
    __shared__ float sh[9];
    const size_t row = blockIdx.x;
    const int t = threadIdx.x;
    const float4 v = *((const float4*)(g_z + row * HID2) + t);

    float s = v.x + v.y + v.z + v.w;
    const float mu = block_reduce_256(s, sh) * (1.0f / 1024.0f);

    const float d0 = v.x - mu, d1 = v.y - mu, d2 = v.z - mu, d3 = v.w - mu;
    float sq = d0 * d0 + d1 * d1 + d2 * d2 + d3 * d3;
    const float var = block_reduce_256(sq, sh) * (1.0f / 1024.0f);
    const float rstd = 1.0f / sqrtf(var + 1e-5f);

    const float4 gv = ((const float4*)gamma)[t];
    const float4 bv = ((const float4*)beta)[t];
    const float4 wv = ((const float4*)W2)[t];
    float a = 0.0f, zn;
    zn = d0 * rstd * gv.x + bv.x; if (zn > 0.0f) a += zn * wv.x;
    zn = d1 * rstd * gv.y + bv.y; if (zn > 0.0f) a += zn * wv.y;
    zn = d2 * rstd * gv.z + bv.z; if (zn > 0.0f) a += zn * wv.z;
    zn = d3 * rstd * gv.w + bv.w; if (zn > 0.0f) a += zn * wv.w;
    const float pre = block_reduce_256(a, sh) + b2[0];
    if (t == 0) g_logits[row] = 1.0f / (1.0f + expf(-pre));
}

// ============================================================================
// Kernel 3: segment starts via binary search on sorted batch ids
// ============================================================================
__global__ void seg_starts_kernel(const int* __restrict__ batch) {
    const int g = blockIdx.x * blockDim.x + threadIdx.x;
    if (g > NG) return;
    int lo = 0, hi = NN;
    while (lo < hi) { int mid = (lo + hi) >> 1; if (batch[mid] < g) lo = mid + 1; else hi = mid; }
    g_start[g] = lo;
}

// ============================================================================
// Kernel 4: per-graph top-k keep mask, rank-count formulation.
// Exactly replicates lexsort((-logits, batch)) stable ordering: node i kept iff
// #{j : l_j > l_i  or  (l_j == l_i and j < i)} < ceil(0.9 * n_g).
// ============================================================================
__global__ __launch_bounds__(512) void topk_kernel() {
    __shared__ float sl[1024];
    const int g = blockIdx.x;
    const int s = g_start[g];
    int n = g_start[g + 1] - s;
    if (n > 1024) n = 1024;            // binomial(131072, 1/256): never triggers
    const int k = (9 * n + 9) / 10;    // == ceil(0.9 * n)
    for (int i = threadIdx.x; i < n; i += 512) sl[i] = g_logits[s + i];
    __syncthreads();
    for (int i = threadIdx.x; i < n; i += 512) {
        const float li = sl[i];
        int cnt = 0;
        for (int j = 0; j < n; j++) {
            const float lj = sl[j];
            cnt += (lj > li) || (lj == li && j < i);
        }
        g_keep[s + i] = (cnt < k) ? 1 : 0;
    }
}

// ============================================================================
// Kernel 5: x_new = keep ? x*logit : noise.  One warp stays inside one node
// (64 float4 per node, 32 per warp) -> uniform branch, single-source load.
// ============================================================================
__global__ void finalize_kernel(const float4* __restrict__ x4,
                                const float4* __restrict__ n4,
                                float* __restrict__ out)
{
    const int v = blockIdx.x * blockDim.x + threadIdx.x;   // [0, NN*64)
    const int node = v >> 6;
    const bool kp = g_keep[node] != 0;
    const float4* src = kp ? x4 : n4;
    float4 r = src[v];
    if (kp) { const float l = g_logits[node]; r.x *= l; r.y *= l; r.z *= l; r.w *= l; }
    ((float4*)out)[v] = r;
}

// Kernel 6: logits section + zero edge-mask section
__global__ void tail_kernel(float* __restrict__ out) {
    const int i = blockIdx.x * blockDim.x + threadIdx.x;
    if (i < NN) { out[OFF_L + i] = g_logits[i]; out[OFF_E + i] = 0.0f; }
}

// Kernel 7: edge-touch scatter (idempotent same-value stores; races benign)
__global__ void edge_kernel(const int* __restrict__ ei, float* __restrict__ out) {
    const int e = blockIdx.x * blockDim.x + threadIdx.x;
    if (e < 2 * NE) out[OFF_E + ei[e]] = 1.0f;
}

// ============================================================================
extern "C" void kernel_launch(void* const* d_in, const int* in_sizes, int n_in,
                              void* d_out, int out_size) {
    const float* h     = (const float*)d_in[0];
    const float* x     = (const float*)d_in[1];
    const float* noise = (const float*)d_in[2];
    const float* W1    = (const float*)d_in[3];
    const float* b1    = (const float*)d_in[4];
    const float* gamma = (const float*)d_in[5];
    const float* beta  = (const float*)d_in[6];
    const float* W2    = (const float*)d_in[7];
    const float* b2    = (const float*)d_in[8];
    const int*   batch = (const int*)d_in[9];
    const int*   edges = (const int*)d_in[10];
    float* out = (float*)d_out;
    (void)in_sizes; (void)n_in; (void)out_size;

    gemm1_kernel<<<dim3(8, 1024), 256>>>(h, W1, b1);
    ln_head_kernel<<<NN, 256>>>(gamma, beta, W2, b2);
    seg_starts_kernel<<<1, 512>>>(batch);
    topk_kernel<<<NG, 512>>>();
    finalize_kernel<<<(NN * 64) / 256, 256>>>((const float4*)x, (const float4*)noise, out);
    tail_kernel<<<NN / 256, 256>>>(out);
    edge_kernel<<<(2 * NE) / 256, 256>>>(edges, out);
}

// round 4
// speedup vs baseline: 1.5010x; 1.5010x over previous
#include <cuda_runtime.h>
#include <cuda_bf16.h>
#include <mma.h>
#include <cstdint>

using namespace nvcuda;

#define NN      131072
#define NG      256
#define HID     512
#define HID2    1024
#define NE      2097152
#define KC      1536                      /* 3 * 512 concatenated K        */
#define OFF_L   ((size_t)NN * 256)
#define OFF_E   (OFF_L + NN)

// -------- scratch (device globals: allocation-free per harness rules) ------
__device__ float          g_z[(size_t)NN * HID2];        // 512 MB
__device__ float          g_logits[NN];
__device__ unsigned char  g_keep[NN];
__device__ int            g_start[NG + 1];
__device__ __align__(16) __nv_bfloat16 g_A[(size_t)NN * KC];    // 384 MB [Ah|Ah|Am]
__device__ __align__(16) __nv_bfloat16 g_B[(size_t)HID2 * KC];  //   3 MB [Bh|Bm|Bh] (B^T rows)

// ============================================================================
// Pre-split: fp32 -> (hi, mid) bf16 residual pair, packed as uint4 of 8 bf16
// ============================================================================
__device__ __forceinline__ void split8_hm(const float* a, uint4& H, uint4& M) {
    unsigned short hb[8], mb[8];
    #pragma unroll
    for (int i = 0; i < 8; i++) {
        float f = a[i];
        __nv_bfloat16 bh = __float2bfloat16_rn(f);
        float r1 = f - __bfloat162float(bh);
        __nv_bfloat16 bm = __float2bfloat16_rn(r1);
        hb[i] = __bfloat16_as_ushort(bh);
        mb[i] = __bfloat16_as_ushort(bm);
    }
    H = make_uint4(hb[0] | (uint32_t)hb[1] << 16, hb[2] | (uint32_t)hb[3] << 16,
                   hb[4] | (uint32_t)hb[5] << 16, hb[6] | (uint32_t)hb[7] << 16);
    M = make_uint4(mb[0] | (uint32_t)mb[1] << 16, mb[2] | (uint32_t)mb[3] << 16,
                   mb[4] | (uint32_t)mb[5] << 16, mb[6] | (uint32_t)mb[7] << 16);
}

// A_cat[row] = [Ah(512) | Ah(512) | Am(512)]
__global__ __launch_bounds__(256) void presplitA_kernel(const float* __restrict__ h) {
    const size_t t = (size_t)blockIdx.x * 256 + threadIdx.x;   // NN*64 threads
    const int row = (int)(t >> 6), kg = (int)(t & 63);         // kg: 8-wide k group
    float a[8];
    *(float4*)&a[0] = *(const float4*)(h + (size_t)row * HID + kg * 8);
    *(float4*)&a[4] = *(const float4*)(h + (size_t)row * HID + kg * 8 + 4);
    uint4 H, M;
    split8_hm(a, H, M);
    __nv_bfloat16* dst = g_A + (size_t)row * KC + kg * 8;
    *(uint4*)(dst)        = H;
    *(uint4*)(dst + 512)  = H;
    *(uint4*)(dst + 1024) = M;
}

// B_cat^T[n] = [Bh(512) | Bm(512) | Bh(512)]   (from W1 [512,1024] fp32)
__global__ __launch_bounds__(256) void presplitB_kernel(const float* __restrict__ W1) {
    const int t = blockIdx.x * 256 + threadIdx.x;              // 65536 threads
    const int n = t >> 6, kg = t & 63;
    float a[8];
    #pragma unroll
    for (int i = 0; i < 8; i++) a[i] = W1[(size_t)(kg * 8 + i) * HID2 + n];
    uint4 H, M;
    split8_hm(a, H, M);
    __nv_bfloat16* dst = g_B + (size_t)n * KC + kg * 8;
    *(uint4*)(dst)        = H;
    *(uint4*)(dst + 512)  = M;
    *(uint4*)(dst + 1024) = H;
}

// ============================================================================
// GEMM: z = A_cat @ B_cat  (131072x1536 @ 1536x1024, bf16 WMMA, fp32 accum)
// CTA 128x128, 8 warps (2x4) of 64x32 warp tiles, k-chunk 64,
// register-staged double buffer, smem padded to 72 halves (LDSM conflict-free).
// ============================================================================
__global__ __launch_bounds__(256, 1) void gemm_wmma_kernel() {
    __shared__ __align__(16) __nv_bfloat16 As[128][72];
    __shared__ __align__(16) __nv_bfloat16 Bs[128][72];

    const int tid = threadIdx.x;
    const int bn = blockIdx.x;            // 8 N-tiles
    const int bm = blockIdx.y;            // 1024 M-tiles
    const int wid = tid >> 5;
    const int wm = wid >> 2;              // 0..1 -> 64-row half
    const int wn = wid & 3;               // 0..3 -> 32-col quarter

    // load map: 128 rows x 8 uint4 (64 bf16) per chunk; lane groups of 8 cover
    // one row's 128B contiguously (full 32B sectors)
    const int r0 = tid >> 3;              // 0..31
    const int c8 = tid & 7;               // 0..7 (uint4 col)
    const __nv_bfloat16* Ag = g_A + (size_t)(bm * 128 + r0) * KC + c8 * 8;
    const __nv_bfloat16* Bg = g_B + (size_t)(bn * 128 + r0) * KC + c8 * 8;

    wmma::fragment<wmma::accumulator, 16, 16, 16, float> acc[4][2];
    #pragma unroll
    for (int i = 0; i < 4; i++)
        #pragma unroll
        for (int j = 0; j < 2; j++) wmma::fill_fragment(acc[i][j], 0.0f);

    uint4 ra[4], rb[4];
    #pragma unroll
    for (int i = 0; i < 4; i++) {
        ra[i] = *(const uint4*)(Ag + (size_t)(32 * i) * KC);
        rb[i] = *(const uint4*)(Bg + (size_t)(32 * i) * KC);
    }

    for (int ck = 0; ck < KC / 64; ck++) {
        #pragma unroll
        for (int i = 0; i < 4; i++) {
            *(uint4*)&As[r0 + 32 * i][c8 * 8] = ra[i];
            *(uint4*)&Bs[r0 + 32 * i][c8 * 8] = rb[i];
        }
        __syncthreads();
        if (ck + 1 < KC / 64) {
            const int ko = (ck + 1) * 64;
            #pragma unroll
            for (int i = 0; i < 4; i++) {
                ra[i] = *(const uint4*)(Ag + (size_t)(32 * i) * KC + ko);
                rb[i] = *(const uint4*)(Bg + (size_t)(32 * i) * KC + ko);
            }
        }
        #pragma unroll
        for (int ks = 0; ks < 4; ks++) {
            wmma::fragment<wmma::matrix_b, 16, 16, 16, __nv_bfloat16, wmma::col_major> bf[2];
            #pragma unroll
            for (int j = 0; j < 2; j++)
                wmma::load_matrix_sync(bf[j], &Bs[wn * 32 + j * 16][ks * 16], 72);
            #pragma unroll
            for (int mi = 0; mi < 4; mi++) {
                wmma::fragment<wmma::matrix_a, 16, 16, 16, __nv_bfloat16, wmma::row_major> af;
                wmma::load_matrix_sync(af, &As[wm * 64 + mi * 16][ks * 16], 72);
                #pragma unroll
                for (int j = 0; j < 2; j++)
                    wmma::mma_sync(acc[mi][j], af, bf[j], acc[mi][j]);
            }
        }
        __syncthreads();
    }

    // epilogue: direct fp32 stores to g_z
    #pragma unroll
    for (int mi = 0; mi < 4; mi++) {
        const size_t row = (size_t)bm * 128 + wm * 64 + mi * 16;
        #pragma unroll
        for (int j = 0; j < 2; j++) {
            const int col = bn * 128 + wn * 32 + j * 16;
            wmma::store_matrix_sync(g_z + row * HID2 + col, acc[mi][j], HID2,
                                    wmma::mem_row_major);
        }
    }
}

// ============================================================================
// LayerNorm -> ReLU -> dot(W2) -> sigmoid (b1 folded in). 1 block / row.
// ============================================================================
__device__ __forceinline__ float block_reduce_256(float v, float* sh) {
    #pragma unroll
    for (int o = 16; o > 0; o >>= 1) v += __shfl_down_sync(0xffffffffu, v, o);
    const int lane = threadIdx.x & 31, w = threadIdx.x >> 5;
    if (lane == 0) sh[w] = v;
    __syncthreads();
    if (threadIdx.x < 32) {
        float t = (threadIdx.x < 8) ? sh[threadIdx.x] : 0.0f;
        #pragma unroll
        for (int o = 4; o > 0; o >>= 1) t += __shfl_down_sync(0xffffffffu, t, o);
        if (threadIdx.x == 0) sh[8] = t;
    }
    __syncthreads();
    float r = sh[8];
    __syncthreads();
    return r;
}

__global__ __launch_bounds__(256) void ln_head_kernel(
    const float* __restrict__ b1,
    const float* __restrict__ gamma, const float* __restrict__ beta,
    const float* __restrict__ W2, const float* __restrict__ b2)
{
    __shared__ float sh[9];
    const size_t row = blockIdx.x;
    const int t = threadIdx.x;
    float4 v = *((const float4*)(g_z + row * HID2) + t);
    const float4 bb = ((const float4*)b1)[t];
    v.x += bb.x; v.y += bb.y; v.z += bb.z; v.w += bb.w;

    float s = v.x + v.y + v.z + v.w;
    const float mu = block_reduce_256(s, sh) * (1.0f / 1024.0f);

    const float d0 = v.x - mu, d1 = v.y - mu, d2 = v.z - mu, d3 = v.w - mu;
    float sq = d0 * d0 + d1 * d1 + d2 * d2 + d3 * d3;
    const float var = block_reduce_256(sq, sh) * (1.0f / 1024.0f);
    const float rstd = 1.0f / sqrtf(var + 1e-5f);

    const float4 gv = ((const float4*)gamma)[t];
    const float4 bv = ((const float4*)beta)[t];
    const float4 wv = ((const float4*)W2)[t];
    float a = 0.0f, zn;
    zn = d0 * rstd * gv.x + bv.x; if (zn > 0.0f) a += zn * wv.x;
    zn = d1 * rstd * gv.y + bv.y; if (zn > 0.0f) a += zn * wv.y;
    zn = d2 * rstd * gv.z + bv.z; if (zn > 0.0f) a += zn * wv.z;
    zn = d3 * rstd * gv.w + bv.w; if (zn > 0.0f) a += zn * wv.w;
    const float pre = block_reduce_256(a, sh) + b2[0];
    if (t == 0) g_logits[row] = 1.0f / (1.0f + expf(-pre));
}

// ============================================================================
__global__ void seg_starts_kernel(const int* __restrict__ batch) {
    const int g = blockIdx.x * blockDim.x + threadIdx.x;
    if (g > NG) return;
    int lo = 0, hi = NN;
    while (lo < hi) { int mid = (lo + hi) >> 1; if (batch[mid] < g) lo = mid + 1; else hi = mid; }
    g_start[g] = lo;
}

// per-graph top-k keep mask, rank-count formulation (stable lexsort semantics)
__global__ __launch_bounds__(512) void topk_kernel() {
    __shared__ float sl[1024];
    const int g = blockIdx.x;
    const int s = g_start[g];
    int n = g_start[g + 1] - s;
    if (n > 1024) n = 1024;
    const int k = (9 * n + 9) / 10;            // ceil(0.9 n)
    for (int i = threadIdx.x; i < n; i += 512) sl[i] = g_logits[s + i];
    __syncthreads();
    for (int i = threadIdx.x; i < n; i += 512) {
        const float li = sl[i];
        int cnt = 0;
        for (int j = 0; j < n; j++) {
            const float lj = sl[j];
            cnt += (lj > li) || (lj == li && j < i);
        }
        g_keep[s + i] = (cnt < k) ? 1 : 0;
    }
}

__global__ void finalize_kernel(const float4* __restrict__ x4,
                                const float4* __restrict__ n4,
                                float* __restrict__ out)
{
    const int v = blockIdx.x * blockDim.x + threadIdx.x;
    const int node = v >> 6;
    const bool kp = g_keep[node] != 0;
    const float4* src = kp ? x4 : n4;
    float4 r = src[v];
    if (kp) { const float l = g_logits[node]; r.x *= l; r.y *= l; r.z *= l; r.w *= l; }
    ((float4*)out)[v] = r;
}

__global__ void tail_kernel(float* __restrict__ out) {
    const int i = blockIdx.x * blockDim.x + threadIdx.x;
    if (i < NN) { out[OFF_L + i] = g_logits[i]; out[OFF_E + i] = 0.0f; }
}

__global__ void edge_kernel(const int* __restrict__ ei, float* __restrict__ out) {
    const int e = blockIdx.x * blockDim.x + threadIdx.x;
    if (e < 2 * NE) out[OFF_E + ei[e]] = 1.0f;
}

// ============================================================================
extern "C" void kernel_launch(void* const* d_in, const int* in_sizes, int n_in,
                              void* d_out, int out_size) {
    const float* h     = (const float*)d_in[0];
    const float* x     = (const float*)d_in[1];
    const float* noise = (const float*)d_in[2];
    const float* W1    = (const float*)d_in[3];
    const float* b1    = (const float*)d_in[4];
    const float* gamma = (const float*)d_in[5];
    const float* beta  = (const float*)d_in[6];
    const float* W2    = (const float*)d_in[7];
    const float* b2    = (const float*)d_in[8];
    const int*   batch = (const int*)d_in[9];
    const int*   edges = (const int*)d_in[10];
    float* out = (float*)d_out;
    (void)in_sizes; (void)n_in; (void)out_size;

    presplitA_kernel<<<(NN * 64) / 256, 256>>>(h);
    presplitB_kernel<<<(HID2 * 64) / 256, 256>>>(W1);
    gemm_wmma_kernel<<<dim3(8, 1024), 256>>>();
    ln_head_kernel<<<NN, 256>>>(b1, gamma, beta, W2, b2);
    seg_starts_kernel<<<1, 512>>>(batch);
    topk_kernel<<<NG, 512>>>();
    finalize_kernel<<<(NN * 64) / 256, 256>>>((const float4*)x, (const float4*)noise, out);
    tail_kernel<<<NN / 256, 256>>>(out);
    edge_kernel<<<(2 * NE) / 256, 256>>>(edges, out);
}

// round 5
// speedup vs baseline: 2.1467x; 1.4302x over previous
#include <cuda_runtime.h>
#include <cuda_bf16.h>
#include <mma.h>
#include <cstdint>

using namespace nvcuda;

#define NN      131072
#define NG      256
#define HID     512
#define HID2    1024
#define NE      2097152
#define OFF_L   ((size_t)NN * 256)
#define OFF_E   (OFF_L + NN)

// -------- scratch (device globals: allocation-free per harness rules) ------
__device__ float          g_z[(size_t)NN * HID2];        // 512 MB
__device__ float          g_logits[NN];
__device__ unsigned char  g_keep[NN];
__device__ int            g_start[NG + 1];
__device__ __align__(16) __nv_bfloat16 g_A[(size_t)NN * 1024];    // 256 MB [Ah|Am]
__device__ __align__(16) __nv_bfloat16 g_B[(size_t)HID2 * 1024];  //   2 MB [Bh|Bm] (B^T rows)

// ======================= PTX helpers ========================================
__device__ __forceinline__ uint32_t smem_u32(const void* p) {
    uint32_t a;
    asm("{ .reg .u64 t; cvta.to.shared.u64 t, %1; cvt.u32.u64 %0, t; }" : "=r"(a) : "l"(p));
    return a;
}
__device__ __forceinline__ void cp16(void* sdst, const void* gsrc) {
    asm volatile("cp.async.cg.shared.global [%0], [%1], 16;"
                 :: "r"(smem_u32(sdst)), "l"(gsrc) : "memory");
}
#define CP_COMMIT()  asm volatile("cp.async.commit_group;" ::: "memory")
#define CP_WAIT(n)   asm volatile("cp.async.wait_group %0;" :: "n"(n) : "memory")

// ============================================================================
// Pre-split: fp32 -> (hi, mid) bf16 residual pair
// ============================================================================
__device__ __forceinline__ void split8_hm(const float* a, uint4& H, uint4& M) {
    unsigned short hb[8], mb[8];
    #pragma unroll
    for (int i = 0; i < 8; i++) {
        float f = a[i];
        __nv_bfloat16 bh = __float2bfloat16_rn(f);
        float r1 = f - __bfloat162float(bh);
        __nv_bfloat16 bm = __float2bfloat16_rn(r1);
        hb[i] = __bfloat16_as_ushort(bh);
        mb[i] = __bfloat16_as_ushort(bm);
    }
    H = make_uint4(hb[0] | (uint32_t)hb[1] << 16, hb[2] | (uint32_t)hb[3] << 16,
                   hb[4] | (uint32_t)hb[5] << 16, hb[6] | (uint32_t)hb[7] << 16);
    M = make_uint4(mb[0] | (uint32_t)mb[1] << 16, mb[2] | (uint32_t)mb[3] << 16,
                   mb[4] | (uint32_t)mb[5] << 16, mb[6] | (uint32_t)mb[7] << 16);
}

__global__ __launch_bounds__(256) void presplitA_kernel(const float* __restrict__ h) {
    const size_t t = (size_t)blockIdx.x * 256 + threadIdx.x;   // NN*64 threads
    const int row = (int)(t >> 6), kg = (int)(t & 63);
    float a[8];
    *(float4*)&a[0] = *(const float4*)(h + (size_t)row * HID + kg * 8);
    *(float4*)&a[4] = *(const float4*)(h + (size_t)row * HID + kg * 8 + 4);
    uint4 H, M;
    split8_hm(a, H, M);
    __nv_bfloat16* dst = g_A + (size_t)row * 1024 + kg * 8;
    *(uint4*)(dst)       = H;
    *(uint4*)(dst + 512) = M;
}

__global__ __launch_bounds__(256) void presplitB_kernel(const float* __restrict__ W1) {
    const int t = blockIdx.x * 256 + threadIdx.x;              // 65536 threads
    const int n = t >> 6, kg = t & 63;
    float a[8];
    #pragma unroll
    for (int i = 0; i < 8; i++) a[i] = W1[(size_t)(kg * 8 + i) * HID2 + n];
    uint4 H, M;
    split8_hm(a, H, M);
    __nv_bfloat16* dst = g_B + (size_t)n * 1024 + kg * 8;
    *(uint4*)(dst)       = H;
    *(uint4*)(dst + 512) = M;
}

// ============================================================================
// GEMM: z = Ah@Bh + Ah@Bm + Am@Bh  (24 logical K-chunks of 64 over 3 sections)
// CTA 256x128, 8 warps (4x2) of 64x64 warp tiles, cp.async 2-stage pipeline.
// ============================================================================
#define LDA 72                      /* padded smem row, halves */
#define A_H (256 * LDA)             /* halves per A stage */
#define B_H (128 * LDA)
#define STG_H (A_H + B_H)

__global__ __launch_bounds__(256, 1) void gemm_wmma_kernel() {
    extern __shared__ __align__(16) __nv_bfloat16 sm[];

    const int tid = threadIdx.x;
    const int bn = blockIdx.x;            // 8 tiles of N=1024
    const int bm = blockIdx.y;            // 512 tiles of M=131072
    const int wid = tid >> 5;
    const int wm = wid >> 1;              // 0..3 -> 64-row slice of 256
    const int wn = wid & 1;               // 0..1 -> 64-col slice of 128

    const int r0 = tid >> 3;              // 0..31
    const int c16 = tid & 7;              // 16B column within 128B k-row
    const __nv_bfloat16* Abase = g_A + (size_t)(bm * 256 + r0) * 1024 + c16 * 8;
    const __nv_bfloat16* Bbase = g_B + (size_t)(bn * 128 + r0) * 1024 + c16 * 8;

    // per-chunk section offsets: hh(A0,B0) hm(A0,B512) mh(A512,B0)
    auto issue = [&](int cc, int buf) {
        const int sec = cc >> 3, koff = (cc & 7) << 6;
        const int aoff = ((sec == 2) ? 512 : 0) + koff;
        const int boff = ((sec == 1) ? 512 : 0) + koff;
        __nv_bfloat16* As = sm + buf * STG_H;
        __nv_bfloat16* Bs = sm + buf * STG_H + A_H;
        #pragma unroll
        for (int i = 0; i < 8; i++)
            cp16(As + (r0 + 32 * i) * LDA + c16 * 8, Abase + (size_t)(32 * i) * 1024 + aoff);
        #pragma unroll
        for (int i = 0; i < 4; i++)
            cp16(Bs + (r0 + 32 * i) * LDA + c16 * 8, Bbase + (size_t)(32 * i) * 1024 + boff);
    };

    wmma::fragment<wmma::accumulator, 16, 16, 16, float> acc[4][4];
    #pragma unroll
    for (int i = 0; i < 4; i++)
        #pragma unroll
        for (int j = 0; j < 4; j++) wmma::fill_fragment(acc[i][j], 0.0f);

    issue(0, 0);
    CP_COMMIT();

    for (int c = 0; c < 24; c++) {
        const int buf = c & 1;
        if (c + 1 < 24) { issue(c + 1, buf ^ 1); CP_COMMIT(); CP_WAIT(1); }
        else            { CP_WAIT(0); }
        __syncthreads();

        const __nv_bfloat16* As = sm + buf * STG_H;
        const __nv_bfloat16* Bs = sm + buf * STG_H + A_H;
        #pragma unroll
        for (int ks = 0; ks < 4; ks++) {
            wmma::fragment<wmma::matrix_b, 16, 16, 16, __nv_bfloat16, wmma::col_major> bf[4];
            #pragma unroll
            for (int j = 0; j < 4; j++)
                wmma::load_matrix_sync(bf[j], Bs + (wn * 64 + j * 16) * LDA + ks * 16, LDA);
            #pragma unroll
            for (int mi = 0; mi < 4; mi++) {
                wmma::fragment<wmma::matrix_a, 16, 16, 16, __nv_bfloat16, wmma::row_major> af;
                wmma::load_matrix_sync(af, As + (wm * 64 + mi * 16) * LDA + ks * 16, LDA);
                #pragma unroll
                for (int j = 0; j < 4; j++)
                    wmma::mma_sync(acc[mi][j], af, bf[j], acc[mi][j]);
            }
        }
        __syncthreads();   // all warps done reading buf before it is refilled
    }

    #pragma unroll
    for (int mi = 0; mi < 4; mi++) {
        const size_t row = (size_t)bm * 256 + wm * 64 + mi * 16;
        #pragma unroll
        for (int j = 0; j < 4; j++) {
            const int col = bn * 128 + wn * 64 + j * 16;
            wmma::store_matrix_sync(g_z + row * HID2 + col, acc[mi][j], HID2,
                                    wmma::mem_row_major);
        }
    }
}

// ============================================================================
// LayerNorm -> ReLU -> dot(W2) -> sigmoid, warp-per-row, shuffle-only.
// ============================================================================
__device__ __forceinline__ float warp_sum(float v) {
    #pragma unroll
    for (int o = 16; o > 0; o >>= 1) v += __shfl_xor_sync(0xffffffffu, v, o);
    return v;
}

__global__ __launch_bounds__(256) void ln_head_kernel(
    const float* __restrict__ b1,
    const float* __restrict__ gamma, const float* __restrict__ beta,
    const float* __restrict__ W2, const float* __restrict__ b2)
{
    const int lane = threadIdx.x & 31;
    const size_t row = (size_t)blockIdx.x * 8 + (threadIdx.x >> 5);
    const float4* zr = (const float4*)(g_z + row * HID2);
    const float4* bp = (const float4*)b1;

    float4 v[8];
    float s = 0.0f;
    #pragma unroll
    for (int j = 0; j < 8; j++) {
        float4 t = zr[j * 32 + lane];
        const float4 bb = bp[j * 32 + lane];
        t.x += bb.x; t.y += bb.y; t.z += bb.z; t.w += bb.w;
        v[j] = t;
        s += t.x + t.y + t.z + t.w;
    }
    const float mu = warp_sum(s) * (1.0f / 1024.0f);

    float sq = 0.0f;
    #pragma unroll
    for (int j = 0; j < 8; j++) {
        const float d0 = v[j].x - mu, d1 = v[j].y - mu, d2 = v[j].z - mu, d3 = v[j].w - mu;
        sq += d0 * d0 + d1 * d1 + d2 * d2 + d3 * d3;
    }
    const float rstd = rsqrtf(warp_sum(sq) * (1.0f / 1024.0f) + 1e-5f);

    float a = 0.0f;
    #pragma unroll
    for (int j = 0; j < 8; j++) {
        const float4 gv = ((const float4*)gamma)[j * 32 + lane];
        const float4 bv = ((const float4*)beta)[j * 32 + lane];
        const float4 wv = ((const float4*)W2)[j * 32 + lane];
        float zn;
        zn = (v[j].x - mu) * rstd * gv.x + bv.x; if (zn > 0.0f) a += zn * wv.x;
        zn = (v[j].y - mu) * rstd * gv.y + bv.y; if (zn > 0.0f) a += zn * wv.y;
        zn = (v[j].z - mu) * rstd * gv.z + bv.z; if (zn > 0.0f) a += zn * wv.z;
        zn = (v[j].w - mu) * rstd * gv.w + bv.w; if (zn > 0.0f) a += zn * wv.w;
    }
    const float pre = warp_sum(a) + b2[0];
    if (lane == 0) g_logits[row] = 1.0f / (1.0f + expf(-pre));
}

// ============================================================================
__global__ void seg_starts_kernel(const int* __restrict__ batch) {
    const int g = blockIdx.x * blockDim.x + threadIdx.x;
    if (g > NG) return;
    int lo = 0, hi = NN;
    while (lo < hi) { int mid = (lo + hi) >> 1; if (batch[mid] < g) lo = mid + 1; else hi = mid; }
    g_start[g] = lo;
}

__global__ __launch_bounds__(512) void topk_kernel() {
    __shared__ float sl[1024];
    const int g = blockIdx.x;
    const int s = g_start[g];
    int n = g_start[g + 1] - s;
    if (n > 1024) n = 1024;
    const int k = (9 * n + 9) / 10;            // ceil(0.9 n)
    for (int i = threadIdx.x; i < n; i += 512) sl[i] = g_logits[s + i];
    __syncthreads();
    for (int i = threadIdx.x; i < n; i += 512) {
        const float li = sl[i];
        int cnt = 0;
        for (int j = 0; j < n; j++) {
            const float lj = sl[j];
            cnt += (lj > li) || (lj == li && j < i);
        }
        g_keep[s + i] = (cnt < k) ? 1 : 0;
    }
}

__global__ void finalize_kernel(const float4* __restrict__ x4,
                                const float4* __restrict__ n4,
                                float* __restrict__ out)
{
    const int v = blockIdx.x * blockDim.x + threadIdx.x;
    const int node = v >> 6;
    const bool kp = g_keep[node] != 0;
    const float4* src = kp ? x4 : n4;
    float4 r = src[v];
    if (kp) { const float l = g_logits[node]; r.x *= l; r.y *= l; r.z *= l; r.w *= l; }
    ((float4*)out)[v] = r;
}

__global__ void tail_kernel(float* __restrict__ out) {
    const int i = blockIdx.x * blockDim.x + threadIdx.x;
    if (i < NN) { out[OFF_L + i] = g_logits[i]; out[OFF_E + i] = 0.0f; }
}

__global__ void edge_kernel(const int* __restrict__ ei, float* __restrict__ out) {
    const int e = blockIdx.x * blockDim.x + threadIdx.x;
    if (e < 2 * NE) out[OFF_E + ei[e]] = 1.0f;
}

// ============================================================================
extern "C" void kernel_launch(void* const* d_in, const int* in_sizes, int n_in,
                              void* d_out, int out_size) {
    const float* h     = (const float*)d_in[0];
    const float* x     = (const float*)d_in[1];
    const float* noise = (const float*)d_in[2];
    const float* W1    = (const float*)d_in[3];
    const float* b1    = (const float*)d_in[4];
    const float* gamma = (const float*)d_in[5];
    const float* beta  = (const float*)d_in[6];
    const float* W2    = (const float*)d_in[7];
    const float* b2    = (const float*)d_in[8];
    const int*   batch = (const int*)d_in[9];
    const int*   edges = (const int*)d_in[10];
    float* out = (float*)d_out;
    (void)in_sizes; (void)n_in; (void)out_size;

    const int dyn = 2 * STG_H * (int)sizeof(__nv_bfloat16);   // 184320 B
    cudaFuncSetAttribute(gemm_wmma_kernel, cudaFuncAttributeMaxDynamicSharedMemorySize, dyn);

    presplitA_kernel<<<(NN * 64) / 256, 256>>>(h);
    presplitB_kernel<<<(HID2 * 64) / 256, 256>>>(W1);
    gemm_wmma_kernel<<<dim3(8, 512), 256, dyn>>>();
    ln_head_kernel<<<NN / 8, 256>>>(b1, gamma, beta, W2, b2);
    seg_starts_kernel<<<1, 512>>>(batch);
    topk_kernel<<<NG, 512>>>();
    finalize_kernel<<<(NN * 64) / 256, 256>>>((const float4*)x, (const float4*)noise, out);
    tail_kernel<<<NN / 256, 256>>>(out);
    edge_kernel<<<(2 * NE) / 256, 256>>>(edges, out);
}

// round 6
// speedup vs baseline: 2.3868x; 1.1119x over previous
#include <cuda_runtime.h>
#include <cuda_bf16.h>
#include <mma.h>
#include <cstdint>

using namespace nvcuda;

#define NN      131072
#define NG      256
#define HID     512
#define HID2    1024
#define NE      2097152
#define OFF_L   ((size_t)NN * 256)
#define OFF_E   (OFF_L + NN)

// -------- scratch (device globals: allocation-free per harness rules) ------
__device__ float          g_z[(size_t)NN * HID2];        // 512 MB
__device__ float          g_logits[NN];
__device__ unsigned char  g_keep[NN];
__device__ int            g_start[NG + 1];
__device__ __align__(16) __nv_bfloat16 g_A[(size_t)NN * 1024];    // 256 MB [Ah|Am]
__device__ __align__(16) __nv_bfloat16 g_B[(size_t)HID2 * 1024];  //   2 MB [Bh|Bm] (B^T rows)

// ======================= PTX helpers ========================================
__device__ __forceinline__ uint32_t smem_u32(const void* p) {
    uint32_t a;
    asm("{ .reg .u64 t; cvta.to.shared.u64 t, %1; cvt.u32.u64 %0, t; }" : "=r"(a) : "l"(p));
    return a;
}
__device__ __forceinline__ void cp16(void* sdst, const void* gsrc) {
    asm volatile("cp.async.cg.shared.global [%0], [%1], 16;"
                 :: "r"(smem_u32(sdst)), "l"(gsrc) : "memory");
}
#define CP_COMMIT()  asm volatile("cp.async.commit_group;" ::: "memory")
#define CP_WAIT(n)   asm volatile("cp.async.wait_group %0;" :: "n"(n) : "memory")

// ============================================================================
// Pre-split: fp32 -> (hi, mid) bf16 residual pair
// ============================================================================
__device__ __forceinline__ void split8_hm(const float* a, uint4& H, uint4& M) {
    unsigned short hb[8], mb[8];
    #pragma unroll
    for (int i = 0; i < 8; i++) {
        float f = a[i];
        __nv_bfloat16 bh = __float2bfloat16_rn(f);
        float r1 = f - __bfloat162float(bh);
        __nv_bfloat16 bm = __float2bfloat16_rn(r1);
        hb[i] = __bfloat16_as_ushort(bh);
        mb[i] = __bfloat16_as_ushort(bm);
    }
    H = make_uint4(hb[0] | (uint32_t)hb[1] << 16, hb[2] | (uint32_t)hb[3] << 16,
                   hb[4] | (uint32_t)hb[5] << 16, hb[6] | (uint32_t)hb[7] << 16);
    M = make_uint4(mb[0] | (uint32_t)mb[1] << 16, mb[2] | (uint32_t)mb[3] << 16,
                   mb[4] | (uint32_t)mb[5] << 16, mb[6] | (uint32_t)mb[7] << 16);
}

__global__ __launch_bounds__(256) void presplitA_kernel(const float* __restrict__ h) {
    const size_t t = (size_t)blockIdx.x * 256 + threadIdx.x;   // NN*64 threads
    const int row = (int)(t >> 6), kg = (int)(t & 63);
    float a[8];
    *(float4*)&a[0] = *(const float4*)(h + (size_t)row * HID + kg * 8);
    *(float4*)&a[4] = *(const float4*)(h + (size_t)row * HID + kg * 8 + 4);
    uint4 H, M;
    split8_hm(a, H, M);
    __nv_bfloat16* dst = g_A + (size_t)row * 1024 + kg * 8;
    *(uint4*)(dst)       = H;
    *(uint4*)(dst + 512) = M;
}

__global__ __launch_bounds__(256) void presplitB_kernel(const float* __restrict__ W1) {
    const int t = blockIdx.x * 256 + threadIdx.x;              // 65536 threads
    const int n = t >> 6, kg = t & 63;
    float a[8];
    #pragma unroll
    for (int i = 0; i < 8; i++) a[i] = W1[(size_t)(kg * 8 + i) * HID2 + n];
    uint4 H, M;
    split8_hm(a, H, M);
    __nv_bfloat16* dst = g_B + (size_t)n * 1024 + kg * 8;
    *(uint4*)(dst)       = H;
    *(uint4*)(dst + 512) = M;
}

// ============================================================================
// GEMM: z = Ah@Bh + Ah@Bm + Am@Bh.
// Superstage = one k-octet (K=64): load {Ah,Am,Bh,Bm} once (96KB), compute all
// 3 products from it. 8 superstages, 2-stage cp.async pipeline, 16 barriers.
// CTA 256x128, 8 warps (4x2), warp tile 64x64.
// ============================================================================
#define LDA 72
#define AH_H (256 * LDA)                 /* halves per A section */
#define BH_H (128 * LDA)
#define SS_H (2 * AH_H + 2 * BH_H)       /* 55296 halves = 110592 B / stage */

__global__ __launch_bounds__(256, 1) void gemm_wmma_kernel() {
    extern __shared__ __align__(16) __nv_bfloat16 sm[];

    const int tid = threadIdx.x;
    const int bn = blockIdx.x;            // 8 tiles of N=1024
    const int bm = blockIdx.y;            // 512 tiles of M=131072
    const int wid = tid >> 5;
    const int wm = wid >> 1;              // 0..3 -> 64-row slice of 256
    const int wn = wid & 1;               // 0..1 -> 64-col slice of 128

    const int r0 = tid >> 3;              // 0..31
    const int c16 = tid & 7;
    const __nv_bfloat16* Abase = g_A + (size_t)(bm * 256 + r0) * 1024 + c16 * 8;
    const __nv_bfloat16* Bbase = g_B + (size_t)(bn * 128 + r0) * 1024 + c16 * 8;

    // superstage fill: Ah, Am, Bh, Bm for k-octet kk
    auto issue = [&](int kk, int buf) {
        const int koff = kk << 6;
        __nv_bfloat16* S = sm + buf * SS_H;
        #pragma unroll
        for (int i = 0; i < 8; i++) {
            cp16(S +          (r0 + 32 * i) * LDA + c16 * 8,
                 Abase + (size_t)(32 * i) * 1024 + koff);          // Ah
            cp16(S + AH_H +   (r0 + 32 * i) * LDA + c16 * 8,
                 Abase + (size_t)(32 * i) * 1024 + 512 + koff);    // Am
        }
        #pragma unroll
        for (int i = 0; i < 4; i++) {
            cp16(S + 2 * AH_H +        (r0 + 32 * i) * LDA + c16 * 8,
                 Bbase + (size_t)(32 * i) * 1024 + koff);          // Bh
            cp16(S + 2 * AH_H + BH_H + (r0 + 32 * i) * LDA + c16 * 8,
                 Bbase + (size_t)(32 * i) * 1024 + 512 + koff);    // Bm
        }
    };

    wmma::fragment<wmma::accumulator, 16, 16, 16, float> acc[4][4];
    #pragma unroll
    for (int i = 0; i < 4; i++)
        #pragma unroll
        for (int j = 0; j < 4; j++) wmma::fill_fragment(acc[i][j], 0.0f);

    issue(0, 0);
    CP_COMMIT();

    for (int kk = 0; kk < 8; kk++) {
        const int buf = kk & 1;
        if (kk + 1 < 8) { issue(kk + 1, buf ^ 1); CP_COMMIT(); CP_WAIT(1); }
        else            { CP_WAIT(0); }
        __syncthreads();

        const __nv_bfloat16* S = sm + buf * SS_H;
        // products: p=0 hh(Ah,Bh), p=1 hm(Ah,Bm), p=2 mh(Am,Bh)
        #pragma unroll
        for (int p = 0; p < 3; p++) {
            const __nv_bfloat16* As = S + ((p == 2) ? AH_H : 0);
            const __nv_bfloat16* Bs = S + 2 * AH_H + ((p == 1) ? BH_H : 0);
            #pragma unroll
            for (int ks = 0; ks < 4; ks++) {
                wmma::fragment<wmma::matrix_b, 16, 16, 16, __nv_bfloat16, wmma::col_major> bf[4];
                #pragma unroll
                for (int j = 0; j < 4; j++)
                    wmma::load_matrix_sync(bf[j], Bs + (wn * 64 + j * 16) * LDA + ks * 16, LDA);
                #pragma unroll
                for (int mi = 0; mi < 4; mi++) {
                    wmma::fragment<wmma::matrix_a, 16, 16, 16, __nv_bfloat16, wmma::row_major> af;
                    wmma::load_matrix_sync(af, As + (wm * 64 + mi * 16) * LDA + ks * 16, LDA);
                    #pragma unroll
                    for (int j = 0; j < 4; j++)
                        wmma::mma_sync(acc[mi][j], af, bf[j], acc[mi][j]);
                }
            }
        }
        __syncthreads();
    }

    #pragma unroll
    for (int mi = 0; mi < 4; mi++) {
        const size_t row = (size_t)bm * 256 + wm * 64 + mi * 16;
        #pragma unroll
        for (int j = 0; j < 4; j++) {
            const int col = bn * 128 + wn * 64 + j * 16;
            wmma::store_matrix_sync(g_z + row * HID2 + col, acc[mi][j], HID2,
                                    wmma::mem_row_major);
        }
    }
}

// ============================================================================
// LayerNorm -> ReLU -> dot(W2) -> sigmoid, warp-per-row, shuffle-only.
// ============================================================================
__device__ __forceinline__ float warp_sum(float v) {
    #pragma unroll
    for (int o = 16; o > 0; o >>= 1) v += __shfl_xor_sync(0xffffffffu, v, o);
    return v;
}

__global__ __launch_bounds__(256) void ln_head_kernel(
    const float* __restrict__ b1,
    const float* __restrict__ gamma, const float* __restrict__ beta,
    const float* __restrict__ W2, const float* __restrict__ b2)
{
    const int lane = threadIdx.x & 31;
    const size_t row = (size_t)blockIdx.x * 8 + (threadIdx.x >> 5);
    const float4* zr = (const float4*)(g_z + row * HID2);
    const float4* bp = (const float4*)b1;

    float4 v[8];
    float s = 0.0f;
    #pragma unroll
    for (int j = 0; j < 8; j++) {
        float4 t = zr[j * 32 + lane];
        const float4 bb = bp[j * 32 + lane];
        t.x += bb.x; t.y += bb.y; t.z += bb.z; t.w += bb.w;
        v[j] = t;
        s += t.x + t.y + t.z + t.w;
    }
    const float mu = warp_sum(s) * (1.0f / 1024.0f);

    float sq = 0.0f;
    #pragma unroll
    for (int j = 0; j < 8; j++) {
        const float d0 = v[j].x - mu, d1 = v[j].y - mu, d2 = v[j].z - mu, d3 = v[j].w - mu;
        sq += d0 * d0 + d1 * d1 + d2 * d2 + d3 * d3;
    }
    const float rstd = rsqrtf(warp_sum(sq) * (1.0f / 1024.0f) + 1e-5f);

    float a = 0.0f;
    #pragma unroll
    for (int j = 0; j < 8; j++) {
        const float4 gv = ((const float4*)gamma)[j * 32 + lane];
        const float4 bv = ((const float4*)beta)[j * 32 + lane];
        const float4 wv = ((const float4*)W2)[j * 32 + lane];
        float zn;
        zn = (v[j].x - mu) * rstd * gv.x + bv.x; if (zn > 0.0f) a += zn * wv.x;
        zn = (v[j].y - mu) * rstd * gv.y + bv.y; if (zn > 0.0f) a += zn * wv.y;
        zn = (v[j].z - mu) * rstd * gv.z + bv.z; if (zn > 0.0f) a += zn * wv.z;
        zn = (v[j].w - mu) * rstd * gv.w + bv.w; if (zn > 0.0f) a += zn * wv.w;
    }
    const float pre = warp_sum(a) + b2[0];
    if (lane == 0) g_logits[row] = 1.0f / (1.0f + expf(-pre));
}

// ============================================================================
__global__ void seg_starts_kernel(const int* __restrict__ batch) {
    const int g = blockIdx.x * blockDim.x + threadIdx.x;
    if (g > NG) return;
    int lo = 0, hi = NN;
    while (lo < hi) { int mid = (lo + hi) >> 1; if (batch[mid] < g) lo = mid + 1; else hi = mid; }
    g_start[g] = lo;
}

__global__ __launch_bounds__(512) void topk_kernel() {
    __shared__ float sl[1024];
    const int g = blockIdx.x;
    const int s = g_start[g];
    int n = g_start[g + 1] - s;
    if (n > 1024) n = 1024;
    const int k = (9 * n + 9) / 10;            // ceil(0.9 n)
    for (int i = threadIdx.x; i < n; i += 512) sl[i] = g_logits[s + i];
    __syncthreads();
    for (int i = threadIdx.x; i < n; i += 512) {
        const float li = sl[i];
        int cnt = 0;
        for (int j = 0; j < n; j++) {
            const float lj = sl[j];
            cnt += (lj > li) || (lj == li && j < i);
        }
        g_keep[s + i] = (cnt < k) ? 1 : 0;
    }
}

__global__ void finalize_kernel(const float4* __restrict__ x4,
                                const float4* __restrict__ n4,
                                float* __restrict__ out)
{
    const int v = blockIdx.x * blockDim.x + threadIdx.x;
    const int node = v >> 6;
    const bool kp = g_keep[node] != 0;
    const float4* src = kp ? x4 : n4;
    float4 r = src[v];
    if (kp) { const float l = g_logits[node]; r.x *= l; r.y *= l; r.z *= l; r.w *= l; }
    ((float4*)out)[v] = r;
}

__global__ void tail_kernel(float* __restrict__ out) {
    const int i = blockIdx.x * blockDim.x + threadIdx.x;
    if (i < NN) { out[OFF_L + i] = g_logits[i]; out[OFF_E + i] = 0.0f; }
}

__global__ void edge_kernel(const int* __restrict__ ei, float* __restrict__ out) {
    const int e = blockIdx.x * blockDim.x + threadIdx.x;
    if (e < 2 * NE) out[OFF_E + ei[e]] = 1.0f;
}

// ============================================================================
extern "C" void kernel_launch(void* const* d_in, const int* in_sizes, int n_in,
                              void* d_out, int out_size) {
    const float* h     = (const float*)d_in[0];
    const float* x     = (const float*)d_in[1];
    const float* noise = (const float*)d_in[2];
    const float* W1    = (const float*)d_in[3];
    const float* b1    = (const float*)d_in[4];
    const float* gamma = (const float*)d_in[5];
    const float* beta  = (const float*)d_in[6];
    const float* W2    = (const float*)d_in[7];
    const float* b2    = (const float*)d_in[8];
    const int*   batch = (const int*)d_in[9];
    const int*   edges = (const int*)d_in[10];
    float* out = (float*)d_out;
    (void)in_sizes; (void)n_in; (void)out_size;

    const int dyn = 2 * SS_H * (int)sizeof(__nv_bfloat16);   // 221184 B
    cudaFuncSetAttribute(gemm_wmma_kernel, cudaFuncAttributeMaxDynamicSharedMemorySize, dyn);

    presplitA_kernel<<<(NN * 64) / 256, 256>>>(h);
    presplitB_kernel<<<(HID2 * 64) / 256, 256>>>(W1);
    gemm_wmma_kernel<<<dim3(8, 512), 256, dyn>>>();
    ln_head_kernel<<<NN / 8, 256>>>(b1, gamma, beta, W2, b2);
    seg_starts_kernel<<<1, 512>>>(batch);
    topk_kernel<<<NG, 512>>>();
    finalize_kernel<<<(NN * 64) / 256, 256>>>((const float4*)x, (const float4*)noise, out);
    tail_kernel<<<NN / 256, 256>>>(out);
    edge_kernel<<<(2 * NE) / 256, 256>>>(edges, out);
}

// round 7
// speedup vs baseline: 2.5577x; 1.0716x over previous
#include <cuda_runtime.h>
#include <cuda_bf16.h>
#include <mma.h>
#include <cstdint>

using namespace nvcuda;

#define NN      131072
#define NG      256
#define HID     512
#define HID2    1024
#define NE      2097152
#define OFF_L   ((size_t)NN * 256)
#define OFF_E   (OFF_L + NN)

// -------- scratch (device globals: allocation-free per harness rules) ------
__device__ float          g_z[(size_t)NN * HID2];        // 512 MB
__device__ float          g_logits[NN];
__device__ unsigned char  g_keep[NN];
__device__ int            g_start[NG + 1];
__device__ __align__(16) __nv_bfloat16 g_A[(size_t)NN * 1024];    // 256 MB [Ah|Am]
__device__ __align__(16) __nv_bfloat16 g_B[(size_t)HID2 * 1024];  //   2 MB [Bh|Bm] (B^T rows)

// ======================= PTX helpers ========================================
__device__ __forceinline__ uint32_t smem_u32(const void* p) {
    uint32_t a;
    asm("{ .reg .u64 t; cvta.to.shared.u64 t, %1; cvt.u32.u64 %0, t; }" : "=r"(a) : "l"(p));
    return a;
}
__device__ __forceinline__ void cp16(void* sdst, const void* gsrc) {
    asm volatile("cp.async.cg.shared.global [%0], [%1], 16;"
                 :: "r"(smem_u32(sdst)), "l"(gsrc) : "memory");
}
#define CP_COMMIT()  asm volatile("cp.async.commit_group;" ::: "memory")
#define CP_WAIT(n)   asm volatile("cp.async.wait_group %0;" :: "n"(n) : "memory")

// ============================================================================
// Pre-split: fp32 -> (hi, mid) bf16 residual pair
// ============================================================================
__device__ __forceinline__ void split8_hm(const float* a, uint4& H, uint4& M) {
    unsigned short hb[8], mb[8];
    #pragma unroll
    for (int i = 0; i < 8; i++) {
        float f = a[i];
        __nv_bfloat16 bh = __float2bfloat16_rn(f);
        float r1 = f - __bfloat162float(bh);
        __nv_bfloat16 bm = __float2bfloat16_rn(r1);
        hb[i] = __bfloat16_as_ushort(bh);
        mb[i] = __bfloat16_as_ushort(bm);
    }
    H = make_uint4(hb[0] | (uint32_t)hb[1] << 16, hb[2] | (uint32_t)hb[3] << 16,
                   hb[4] | (uint32_t)hb[5] << 16, hb[6] | (uint32_t)hb[7] << 16);
    M = make_uint4(mb[0] | (uint32_t)mb[1] << 16, mb[2] | (uint32_t)mb[3] << 16,
                   mb[4] | (uint32_t)mb[5] << 16, mb[6] | (uint32_t)mb[7] << 16);
}

__global__ __launch_bounds__(256) void presplitA_kernel(const float* __restrict__ h) {
    const size_t t = (size_t)blockIdx.x * 256 + threadIdx.x;   // NN*64 threads
    const int row = (int)(t >> 6), kg = (int)(t & 63);
    float a[8];
    *(float4*)&a[0] = *(const float4*)(h + (size_t)row * HID + kg * 8);
    *(float4*)&a[4] = *(const float4*)(h + (size_t)row * HID + kg * 8 + 4);
    uint4 H, M;
    split8_hm(a, H, M);
    __nv_bfloat16* dst = g_A + (size_t)row * 1024 + kg * 8;
    *(uint4*)(dst)       = H;
    *(uint4*)(dst + 512) = M;
}

__global__ __launch_bounds__(256) void presplitB_kernel(const float* __restrict__ W1) {
    const int t = blockIdx.x * 256 + threadIdx.x;              // 65536 threads
    const int n = t >> 6, kg = t & 63;
    float a[8];
    #pragma unroll
    for (int i = 0; i < 8; i++) a[i] = W1[(size_t)(kg * 8 + i) * HID2 + n];
    uint4 H, M;
    split8_hm(a, H, M);
    __nv_bfloat16* dst = g_B + (size_t)n * 1024 + kg * 8;
    *(uint4*)(dst)       = H;
    *(uint4*)(dst + 512) = M;
}

// ============================================================================
// GEMM: z = Ah@Bh + Ah@Bm + Am@Bh.
// Superstage = k-octet (K=64): load {Ah,Am,Bh,Bm} once, compute all 3 products.
// Fragment-reuse mainloop: per ks-step load bf_h/bf_m once (shared by all mi),
// and each af_h feeds both hh and hm. 64 frag-loads per superstage (was 96).
// ============================================================================
#define LDA 72
#define AH_H (256 * LDA)
#define BH_H (128 * LDA)
#define SS_H (2 * AH_H + 2 * BH_H)       /* 110592 B per stage */

__global__ __launch_bounds__(256, 1) void gemm_wmma_kernel() {
    extern __shared__ __align__(16) __nv_bfloat16 sm[];

    const int tid = threadIdx.x;
    const int bn = blockIdx.x;            // 8 tiles of N=1024
    const int bm = blockIdx.y;            // 512 tiles of M=131072
    const int wid = tid >> 5;
    const int wm = wid >> 1;              // 0..3 -> 64-row slice of 256
    const int wn = wid & 1;               // 0..1 -> 64-col slice of 128

    const int r0 = tid >> 3;
    const int c16 = tid & 7;
    const __nv_bfloat16* Abase = g_A + (size_t)(bm * 256 + r0) * 1024 + c16 * 8;
    const __nv_bfloat16* Bbase = g_B + (size_t)(bn * 128 + r0) * 1024 + c16 * 8;

    auto issue = [&](int kk, int buf) {
        const int koff = kk << 6;
        __nv_bfloat16* S = sm + buf * SS_H;
        #pragma unroll
        for (int i = 0; i < 8; i++) {
            cp16(S +        (r0 + 32 * i) * LDA + c16 * 8,
                 Abase + (size_t)(32 * i) * 1024 + koff);          // Ah
            cp16(S + AH_H + (r0 + 32 * i) * LDA + c16 * 8,
                 Abase + (size_t)(32 * i) * 1024 + 512 + koff);    // Am
        }
        #pragma unroll
        for (int i = 0; i < 4; i++) {
            cp16(S + 2 * AH_H +        (r0 + 32 * i) * LDA + c16 * 8,
                 Bbase + (size_t)(32 * i) * 1024 + koff);          // Bh
            cp16(S + 2 * AH_H + BH_H + (r0 + 32 * i) * LDA + c16 * 8,
                 Bbase + (size_t)(32 * i) * 1024 + 512 + koff);    // Bm
        }
    };

    wmma::fragment<wmma::accumulator, 16, 16, 16, float> acc[4][4];
    #pragma unroll
    for (int i = 0; i < 4; i++)
        #pragma unroll
        for (int j = 0; j < 4; j++) wmma::fill_fragment(acc[i][j], 0.0f);

    issue(0, 0);
    CP_COMMIT();

    for (int kk = 0; kk < 8; kk++) {
        const int buf = kk & 1;
        if (kk + 1 < 8) { issue(kk + 1, buf ^ 1); CP_COMMIT(); CP_WAIT(1); }
        else            { CP_WAIT(0); }
        __syncthreads();

        const __nv_bfloat16* Ah = sm + buf * SS_H;
        const __nv_bfloat16* Am = Ah + AH_H;
        const __nv_bfloat16* Bh = Ah + 2 * AH_H;
        const __nv_bfloat16* Bm = Bh + BH_H;

        #pragma unroll
        for (int ks = 0; ks < 4; ks++) {
            wmma::fragment<wmma::matrix_b, 16, 16, 16, __nv_bfloat16, wmma::col_major> bh[4], bmf[4];
            #pragma unroll
            for (int j = 0; j < 4; j++) {
                wmma::load_matrix_sync(bh[j],  Bh + (wn * 64 + j * 16) * LDA + ks * 16, LDA);
                wmma::load_matrix_sync(bmf[j], Bm + (wn * 64 + j * 16) * LDA + ks * 16, LDA);
            }
            #pragma unroll
            for (int mi = 0; mi < 4; mi++) {
                wmma::fragment<wmma::matrix_a, 16, 16, 16, __nv_bfloat16, wmma::row_major> af;
                wmma::load_matrix_sync(af, Ah + (wm * 64 + mi * 16) * LDA + ks * 16, LDA);
                #pragma unroll
                for (int j = 0; j < 4; j++) wmma::mma_sync(acc[mi][j], af, bh[j], acc[mi][j]);
                #pragma unroll
                for (int j = 0; j < 4; j++) wmma::mma_sync(acc[mi][j], af, bmf[j], acc[mi][j]);
                wmma::load_matrix_sync(af, Am + (wm * 64 + mi * 16) * LDA + ks * 16, LDA);
                #pragma unroll
                for (int j = 0; j < 4; j++) wmma::mma_sync(acc[mi][j], af, bh[j], acc[mi][j]);
            }
        }
        __syncthreads();
    }

    #pragma unroll
    for (int mi = 0; mi < 4; mi++) {
        const size_t row = (size_t)bm * 256 + wm * 64 + mi * 16;
        #pragma unroll
        for (int j = 0; j < 4; j++) {
            const int col = bn * 128 + wn * 64 + j * 16;
            wmma::store_matrix_sync(g_z + row * HID2 + col, acc[mi][j], HID2,
                                    wmma::mem_row_major);
        }
    }
}

// ============================================================================
// LayerNorm -> ReLU -> dot(W2) -> sigmoid, warp-per-row, shuffle-only.
// ============================================================================
__device__ __forceinline__ float warp_sum(float v) {
    #pragma unroll
    for (int o = 16; o > 0; o >>= 1) v += __shfl_xor_sync(0xffffffffu, v, o);
    return v;
}

__global__ __launch_bounds__(256) void ln_head_kernel(
    const float* __restrict__ b1,
    const float* __restrict__ gamma, const float* __restrict__ beta,
    const float* __restrict__ W2, const float* __restrict__ b2)
{
    const int lane = threadIdx.x & 31;
    const size_t row = (size_t)blockIdx.x * 8 + (threadIdx.x >> 5);
    const float4* zr = (const float4*)(g_z + row * HID2);
    const float4* bp = (const float4*)b1;

    float4 v[8];
    float s = 0.0f;
    #pragma unroll
    for (int j = 0; j < 8; j++) {
        float4 t = zr[j * 32 + lane];
        const float4 bb = bp[j * 32 + lane];
        t.x += bb.x; t.y += bb.y; t.z += bb.z; t.w += bb.w;
        v[j] = t;
        s += t.x + t.y + t.z + t.w;
    }
    const float mu = warp_sum(s) * (1.0f / 1024.0f);

    float sq = 0.0f;
    #pragma unroll
    for (int j = 0; j < 8; j++) {
        const float d0 = v[j].x - mu, d1 = v[j].y - mu, d2 = v[j].z - mu, d3 = v[j].w - mu;
        sq += d0 * d0 + d1 * d1 + d2 * d2 + d3 * d3;
    }
    const float rstd = rsqrtf(warp_sum(sq) * (1.0f / 1024.0f) + 1e-5f);

    float a = 0.0f;
    #pragma unroll
    for (int j = 0; j < 8; j++) {
        const float4 gv = ((const float4*)gamma)[j * 32 + lane];
        const float4 bv = ((const float4*)beta)[j * 32 + lane];
        const float4 wv = ((const float4*)W2)[j * 32 + lane];
        float zn;
        zn = (v[j].x - mu) * rstd * gv.x + bv.x; if (zn > 0.0f) a += zn * wv.x;
        zn = (v[j].y - mu) * rstd * gv.y + bv.y; if (zn > 0.0f) a += zn * wv.y;
        zn = (v[j].z - mu) * rstd * gv.z + bv.z; if (zn > 0.0f) a += zn * wv.z;
        zn = (v[j].w - mu) * rstd * gv.w + bv.w; if (zn > 0.0f) a += zn * wv.w;
    }
    const float pre = warp_sum(a) + b2[0];
    if (lane == 0) g_logits[row] = 1.0f / (1.0f + expf(-pre));
}

// ============================================================================
__global__ void seg_starts_kernel(const int* __restrict__ batch) {
    const int g = blockIdx.x * blockDim.x + threadIdx.x;
    if (g > NG) return;
    int lo = 0, hi = NN;
    while (lo < hi) { int mid = (lo + hi) >> 1; if (batch[mid] < g) lo = mid + 1; else hi = mid; }
    g_start[g] = lo;
}

__global__ __launch_bounds__(512) void topk_kernel() {
    __shared__ float sl[1024];
    const int g = blockIdx.x;
    const int s = g_start[g];
    int n = g_start[g + 1] - s;
    if (n > 1024) n = 1024;
    const int k = (9 * n + 9) / 10;            // ceil(0.9 n)
    for (int i = threadIdx.x; i < n; i += 512) sl[i] = g_logits[s + i];
    __syncthreads();
    for (int i = threadIdx.x; i < n; i += 512) {
        const float li = sl[i];
        int cnt = 0;
        for (int j = 0; j < n; j++) {
            const float lj = sl[j];
            cnt += (lj > li) || (lj == li && j < i);
        }
        g_keep[s + i] = (cnt < k) ? 1 : 0;
    }
}

__global__ void finalize_kernel(const float4* __restrict__ x4,
                                const float4* __restrict__ n4,
                                float* __restrict__ out)
{
    const int v = blockIdx.x * blockDim.x + threadIdx.x;
    const int node = v >> 6;
    const bool kp = g_keep[node] != 0;
    const float4* src = kp ? x4 : n4;
    float4 r = src[v];
    if (kp) { const float l = g_logits[node]; r.x *= l; r.y *= l; r.z *= l; r.w *= l; }
    ((float4*)out)[v] = r;
}

__global__ void tail_kernel(float* __restrict__ out) {
    const int i = blockIdx.x * blockDim.x + threadIdx.x;
    if (i < NN) { out[OFF_L + i] = g_logits[i]; out[OFF_E + i] = 0.0f; }
}

__global__ void edge_kernel(const int* __restrict__ ei, float* __restrict__ out) {
    const int e = blockIdx.x * blockDim.x + threadIdx.x;
    if (e < 2 * NE) out[OFF_E + ei[e]] = 1.0f;
}

// ============================================================================
extern "C" void kernel_launch(void* const* d_in, const int* in_sizes, int n_in,
                              void* d_out, int out_size) {
    const float* h     = (const float*)d_in[0];
    const float* x     = (const float*)d_in[1];
    const float* noise = (const float*)d_in[2];
    const float* W1    = (const float*)d_in[3];
    const float* b1    = (const float*)d_in[4];
    const float* gamma = (const float*)d_in[5];
    const float* beta  = (const float*)d_in[6];
    const float* W2    = (const float*)d_in[7];
    const float* b2    = (const float*)d_in[8];
    const int*   batch = (const int*)d_in[9];
    const int*   edges = (const int*)d_in[10];
    float* out = (float*)d_out;
    (void)in_sizes; (void)n_in; (void)out_size;

    const int dyn = 2 * SS_H * (int)sizeof(__nv_bfloat16);   // 221184 B
    cudaFuncSetAttribute(gemm_wmma_kernel, cudaFuncAttributeMaxDynamicSharedMemorySize, dyn);

    presplitA_kernel<<<(NN * 64) / 256, 256>>>(h);
    presplitB_kernel<<<(HID2 * 64) / 256, 256>>>(W1);
    gemm_wmma_kernel<<<dim3(8, 512), 256, dyn>>>();
    ln_head_kernel<<<NN / 8, 256>>>(b1, gamma, beta, W2, b2);
    seg_starts_kernel<<<1, 512>>>(batch);
    topk_kernel<<<NG, 512>>>();
    finalize_kernel<<<(NN * 64) / 256, 256>>>((const float4*)x, (const float4*)noise, out);
    tail_kernel<<<NN / 256, 256>>>(out);
    edge_kernel<<<(2 * NE) / 256, 256>>>(edges, out);
}